// round 14
// baseline (speedup 1.0000x reference)
#include <cuda_runtime.h>
#include <cuda_fp16.h>
#include <cuda_bf16.h>
#include <cstdint>
#include <math.h>

// Problem constants
#define VSZ 98304
#define SEQ 1536
#define BAT 2
#define DIM 768
#define NH  24
#define DH  32
#define FFD 3072
#define ROWS (SEQ*BAT)        // 3072
#define QKVN (3*DIM)          // 2304
// exp(s*SCALE) = 2^(s*EXP2S), EXP2S = log2(e)/sqrt(32)
#define EXP2S 0.2550348742f

// ---------------- scratch (device globals; no allocations allowed) ----------
__device__ float  g_x  [ROWS * DIM];    // residual stream (fp32)
__device__ __half g_h  [ROWS * DIM];    // LN output (fp16)
__device__ __half g_qkv[ROWS * QKVN];   // qkv projection (fp16)
__device__ __half g_ctx[ROWS * DIM];    // attention context (fp16)
__device__ __half g_mm [ROWS * FFD];    // FC+gelu output (fp16)

// pre-converted fp16 weights: per layer [wqkv | wo | wfc | wproj]
#define WOFF_QKV  0
#define WOFF_WO   (QKVN*DIM)
#define WOFF_FC   (WOFF_WO + DIM*DIM)
#define WOFF_PROJ (WOFF_FC + FFD*DIM)
#define WLAYER    (WOFF_PROJ + DIM*FFD)         // 7077888
__device__ __half g_wh[2 * WLAYER];

__device__ __forceinline__ unsigned int h2u(__half2 h) {
    union { __half2 h; unsigned int u; } cvt;
    cvt.h = h;
    return cvt.u;
}

// ---------------- one-time weight fp32 -> fp16 conversion (single kernel) ----
struct WJobs {
    const float4* src[8];
    unsigned int  end[8];   // cumulative end, in float4 units
};

__global__ void tohalf_all_kernel(WJobs jobs, __half* __restrict__ out) {
    unsigned int i = blockIdx.x * blockDim.x + threadIdx.x;
    if (i >= jobs.end[7]) return;
    int s = 0;
#pragma unroll
    for (int k = 0; k < 7; k++) s += (i >= jobs.end[k]) ? 1 : 0;
    unsigned int base = s ? jobs.end[s - 1] : 0u;
    float4 v = jobs.src[s][i - base];
    __half2* o = (__half2*)out + 2 * (size_t)i;
    o[0] = __floats2half2_rn(v.x, v.y);
    o[1] = __floats2half2_rn(v.z, v.w);
}

// ---------------- embedding ----------------
__global__ void embed_kernel(const int* __restrict__ ids,
                             const float* __restrict__ wte,
                             const float* __restrict__ wpe,
                             float* __restrict__ x) {
    int r = blockIdx.x;            // r = s*B + b
    int s = r / BAT, b = r % BAT;
    int idx = ids[b * SEQ + s];
    const float4* te = (const float4*)(wte + (size_t)idx * DIM);
    const float4* pe = (const float4*)(wpe + (size_t)s * DIM);
    float4* xr = (float4*)(x + (size_t)r * DIM);
    int i = threadIdx.x;           // 192 threads, one float4 each
    float4 a = te[i], p = pe[i];
    xr[i] = make_float4(a.x + p.x, a.y + p.y, a.z + p.z, a.w + p.w);
}

// ---------------- layernorm over D=768 (192 threads x float4) ---------------
template <typename OutT>
__global__ void layernorm_kernel(const float* __restrict__ x,
                                 const float* __restrict__ w,
                                 const float* __restrict__ b,
                                 OutT* __restrict__ out) {
    __shared__ float ssum[6], ssum2[6];
    __shared__ float smu, sinv;
    int r = blockIdx.x;
    int tid = threadIdx.x;                  // 0..191
    float4 v = ((const float4*)(x + (size_t)r * DIM))[tid];
    float s  = (v.x + v.y) + (v.z + v.w);
    float s2 = fmaf(v.x, v.x, fmaf(v.y, v.y, fmaf(v.z, v.z, v.w * v.w)));
#pragma unroll
    for (int o = 16; o; o >>= 1) {
        s  += __shfl_xor_sync(0xffffffffu, s,  o);
        s2 += __shfl_xor_sync(0xffffffffu, s2, o);
    }
    if ((tid & 31) == 0) { ssum[tid >> 5] = s; ssum2[tid >> 5] = s2; }
    __syncthreads();
    if (tid == 0) {
        float S = 0.f, S2 = 0.f;
#pragma unroll
        for (int i = 0; i < 6; i++) { S += ssum[i]; S2 += ssum2[i]; }
        float mu  = S * (1.0f / DIM);
        float var = S2 * (1.0f / DIM) - mu * mu;
        smu = mu;
        sinv = rsqrtf(var + 1e-5f);
    }
    __syncthreads();
    float mu = smu, inv = sinv;
    float4 wv = ((const float4*)w)[tid];
    float4 bv = ((const float4*)b)[tid];
    float o0 = (v.x - mu) * inv * wv.x + bv.x;
    float o1 = (v.y - mu) * inv * wv.y + bv.y;
    float o2 = (v.z - mu) * inv * wv.z + bv.z;
    float o3 = (v.w - mu) * inv * wv.w + bv.w;
    if constexpr (sizeof(OutT) == 2) {
        __half2* orow = (__half2*)(out + (size_t)r * DIM);
        orow[2 * tid]     = __floats2half2_rn(o0, o1);
        orow[2 * tid + 1] = __floats2half2_rn(o2, o3);
    } else {
        ((float4*)(out + (size_t)r * DIM))[tid] = make_float4(o0, o1, o2, o3);
    }
}

// ---------------- fast exp2 on the FMA pipe (no MUFU) ------------------------
// returns 2^t ; caller pre-scales t = score * EXP2S
__device__ __forceinline__ float fast_exp2(float t) {
    float z = t + 12582912.0f;                 // round-to-nearest-int (RN add)
    int   i = __float_as_int(z) - 0x4B400000;  // integer part
    float f = t - (z - 12582912.0f);           // frac in [-0.5, 0.5]
    float p =              1.3333558146e-3f;
    p = fmaf(p, f, 9.6181291076e-3f);
    p = fmaf(p, f, 5.5504108665e-2f);
    p = fmaf(p, f, 2.4022650696e-1f);
    p = fmaf(p, f, 6.9314718056e-1f);
    p = fmaf(p, f, 1.0f);
    return p * __int_as_float((i + 127) << 23);
}

__device__ __forceinline__ void mma_fp16(float* c, const unsigned int* a,
                                         unsigned int b0, unsigned int b1) {
    asm volatile(
        "mma.sync.aligned.m16n8k16.row.col.f32.f16.f16.f32 "
        "{%0,%1,%2,%3}, {%4,%5,%6,%7}, {%8,%9}, {%0,%1,%2,%3};\n"
        : "+f"(c[0]), "+f"(c[1]), "+f"(c[2]), "+f"(c[3])
        : "r"(a[0]), "r"(a[1]), "r"(a[2]), "r"(a[3]), "r"(b0), "r"(b1));
}

__device__ __forceinline__ void ldsm_x4(unsigned int* r, const void* smem) {
    unsigned int addr = (unsigned int)__cvta_generic_to_shared(smem);
    asm volatile(
        "ldmatrix.sync.aligned.m8n8.x4.shared.b16 {%0,%1,%2,%3}, [%4];\n"
        : "=r"(r[0]), "=r"(r[1]), "=r"(r[2]), "=r"(r[3]) : "r"(addr));
}

__device__ __forceinline__ void ldsm_x4_trans(unsigned int* r, const void* smem) {
    unsigned int addr = (unsigned int)__cvta_generic_to_shared(smem);
    asm volatile(
        "ldmatrix.sync.aligned.m8n8.x4.trans.shared.b16 {%0,%1,%2,%3}, [%4];\n"
        : "=r"(r[0]), "=r"(r[1]), "=r"(r[2]), "=r"(r[3]) : "r"(addr));
}

__device__ __forceinline__ void cp_async16(void* smem, const void* gmem) {
    unsigned int s = (unsigned int)__cvta_generic_to_shared(smem);
    asm volatile("cp.async.cg.shared.global [%0], [%1], 16;\n" :: "r"(s), "l"(gmem));
}
#define CP_COMMIT() asm volatile("cp.async.commit_group;\n" ::: "memory")
#define CP_WAIT1()  asm volatile("cp.async.wait_group 1;\n" ::: "memory")

// ---------------- fp16 tensor-core NT GEMM (128x64 tiles, 3 CTA/SM) ----------
// EPI: 0 = bias (OutT=__half), 1 = bias + residual (OutT=float),
//      2 = bias + exact gelu (OutT=__half)
#define HPAD 40
#define ATILE_H (128 * HPAD)              // A halves per stage
#define BTILE_H (64 * HPAD)               // B halves per stage
#define GSMEM_BYTES (3 * (ATILE_H + BTILE_H) * 2)   // 46080 B

template <int EPI, typename OutT>
__global__ void __launch_bounds__(256, 3)
gemm_fp16(const __half* __restrict__ A, const __half* __restrict__ W,
          const float* __restrict__ bias, const float* __restrict__ res,
          OutT* __restrict__ C, int M, int N, int K) {
    extern __shared__ __half sm[];
    // A stage s: sm + s*ATILE_H ; B stage s: sm + 3*ATILE_H + s*BTILE_H

    int m0 = blockIdx.y * 128;
    int n0 = blockIdx.x * 64;
    int tid  = threadIdx.x;
    int warp = tid >> 5, lane = tid & 31;
    int wm = (warp >> 1) * 32;     // 4 warps along M
    int wn = (warp & 1) * 32;      // 2 warps along N
    int g = lane >> 2, t = lane & 3;
    int lrow = lane & 15, lcol = (lane >> 4) * 8;

    float c[2][4][4];
#pragma unroll
    for (int mi = 0; mi < 2; mi++)
#pragma unroll
        for (int nj = 0; nj < 4; nj++)
#pragma unroll
            for (int f = 0; f < 4; f++) c[mi][nj][f] = 0.f;

    int ldrow = tid >> 2, ldc8 = (tid & 3) * 8;   // 64 rows x 4 chunks
    auto load_tile = [&](int s, int k0) {
        __half* As = sm + s * ATILE_H;
        __half* Bs = sm + 3 * ATILE_H + s * BTILE_H;
        cp_async16(&As[ldrow * HPAD + ldc8],
                   &A[(size_t)(m0 + ldrow) * K + k0 + ldc8]);
        cp_async16(&As[(ldrow + 64) * HPAD + ldc8],
                   &A[(size_t)(m0 + ldrow + 64) * K + k0 + ldc8]);
        cp_async16(&Bs[ldrow * HPAD + ldc8],
                   &W[(size_t)(n0 + ldrow) * K + k0 + ldc8]);
    };

    int nk = K >> 5;
    load_tile(0, 0);
    CP_COMMIT();
    load_tile(1, 32);
    CP_COMMIT();

    int s = 0;
    for (int kt = 0; kt < nk; kt++) {
        CP_WAIT1();
        __syncthreads();
        if (kt + 2 < nk) load_tile((s + 2) % 3, (kt + 2) << 5);
        CP_COMMIT();

        const __half* As = sm + s * ATILE_H;
        const __half* Bs = sm + 3 * ATILE_H + s * BTILE_H;
#pragma unroll
        for (int ks = 0; ks < 2; ks++) {
            int k0 = ks * 16 + lcol;
            unsigned int a[2][4], bfr[2][4];
#pragma unroll
            for (int mi = 0; mi < 2; mi++)
                ldsm_x4(a[mi], &As[(wm + mi * 16 + lrow) * HPAD + k0]);
#pragma unroll
            for (int np = 0; np < 2; np++)
                ldsm_x4(bfr[np], &Bs[(wn + np * 16 + lrow) * HPAD + k0]);
#pragma unroll
            for (int mi = 0; mi < 2; mi++)
#pragma unroll
                for (int nj = 0; nj < 4; nj++)
                    mma_fp16(c[mi][nj], a[mi],
                             bfr[nj >> 1][nj & 1], bfr[nj >> 1][(nj & 1) + 2]);
        }
        s = (s + 1) % 3;
    }

#pragma unroll
    for (int mi = 0; mi < 2; mi++) {
        int r0 = m0 + wm + mi * 16 + g;
        int r1 = r0 + 8;
#pragma unroll
        for (int nj = 0; nj < 4; nj++) {
            int col = n0 + wn + nj * 8 + 2 * t;
            float b0 = bias[col], b1 = bias[col + 1];
            float v00 = c[mi][nj][0] + b0, v01 = c[mi][nj][1] + b1;
            float v10 = c[mi][nj][2] + b0, v11 = c[mi][nj][3] + b1;
            if (EPI == 1) {
                v00 += res[(size_t)r0 * N + col];
                v01 += res[(size_t)r0 * N + col + 1];
                v10 += res[(size_t)r1 * N + col];
                v11 += res[(size_t)r1 * N + col + 1];
            }
            if (EPI == 2) {
                v00 = 0.5f * v00 * (1.0f + erff(v00 * 0.7071067811865476f));
                v01 = 0.5f * v01 * (1.0f + erff(v01 * 0.7071067811865476f));
                v10 = 0.5f * v10 * (1.0f + erff(v10 * 0.7071067811865476f));
                v11 = 0.5f * v11 * (1.0f + erff(v11 * 0.7071067811865476f));
            }
            if constexpr (sizeof(OutT) == 2) {
                *(__half2*)&C[(size_t)r0 * N + col] = __floats2half2_rn(v00, v01);
                *(__half2*)&C[(size_t)r1 * N + col] = __floats2half2_rn(v10, v11);
            } else {
                *(float2*)&C[(size_t)r0 * N + col] = make_float2(v00, v01);
                *(float2*)&C[(size_t)r1 * N + col] = make_float2(v10, v11);
            }
        }
    }
}

// ---------------- fp16 MMA causal flash attention ----------------------------
// 1-D grid of 576 blocks; qt = bid/48 so the 4 co-resident blocks per SM
// (bid = r mod 148) get qtiles ~{a, a+3, a+6, a+9} -> balanced causal load.
#define AQB 128
#define AKT 32
#define KPAD 40

__global__ void __launch_bounds__(128, 4)
attention_mma(const __half* __restrict__ qkv, __half* __restrict__ ctx) {
    __shared__ __half Qs[AQB][KPAD];   // used only during init
    __shared__ __half Kt[AKT][KPAD];
    __shared__ __half Vt[AKT][KPAD];

    int u = blockIdx.x;
    int qt = u / (BAT * NH);           // qtile varies SLOWEST
    int bh = u % (BAT * NH);
    int b = bh / NH, h = bh % NH;
    int q0 = qt * AQB;
    int tid = threadIdx.x;
    int warp = tid >> 5, lane = tid & 31;
    int g = lane >> 2, t = lane & 3;
    int lrow = lane & 15, lcol = (lane >> 4) * 8;
    int wq0 = q0 + warp * 32;

    {
        const __half* qp = qkv + ((size_t)(q0 + tid) * BAT + b) * QKVN + h * 96;
#pragma unroll
        for (int i = 0; i < 4; i++)
            *(uint4*)&Qs[tid][i * 8] = *(const uint4*)&qp[i * 8];
    }
    __syncthreads();
    unsigned int qf[2][2][4];          // [mt][kg]
#pragma unroll
    for (int mt = 0; mt < 2; mt++)
#pragma unroll
        for (int kg = 0; kg < 2; kg++)
            ldsm_x4(qf[mt][kg], &Qs[warp * 32 + mt * 16 + lrow][kg * 16 + lcol]);

    float cacc[2][4][4];
#pragma unroll
    for (int mt = 0; mt < 2; mt++)
#pragma unroll
        for (int dt = 0; dt < 4; dt++)
#pragma unroll
            for (int f = 0; f < 4; f++) cacc[mt][dt][f] = 0.f;
    float lsum[2][2] = {{0.f, 0.f}, {0.f, 0.f}};

    int kend = q0 + AQB;
    for (int kt0 = 0; kt0 < kend; kt0 += AKT) {
        __syncthreads();
        {   // stage K,V tile: 32 keys x 32 halves each
            int kk = tid >> 2, c8 = (tid & 3) * 8;
            const __half* kp = qkv + ((size_t)(kt0 + kk) * BAT + b) * QKVN + h * 96;
            *(uint4*)&Kt[kk][c8] = *(const uint4*)&kp[DH + c8];
            *(uint4*)&Vt[kk][c8] = *(const uint4*)&kp[2 * DH + c8];
        }
        __syncthreads();

        if (kt0 > wq0 + 31) continue;

        unsigned int kf[2][2][4];
#pragma unroll
        for (int ntp = 0; ntp < 2; ntp++)
#pragma unroll
            for (int kg = 0; kg < 2; kg++)
                ldsm_x4(kf[ntp][kg], &Kt[ntp * 16 + lrow][kg * 16 + lcol]);

        float sc[2][4][4];
#pragma unroll
        for (int mt = 0; mt < 2; mt++)
#pragma unroll
            for (int nt = 0; nt < 4; nt++)
#pragma unroll
                for (int f = 0; f < 4; f++) sc[mt][nt][f] = 0.f;
#pragma unroll
        for (int mt = 0; mt < 2; mt++)
#pragma unroll
            for (int nt = 0; nt < 4; nt++)
#pragma unroll
                for (int kg = 0; kg < 2; kg++)
                    mma_fp16(sc[mt][nt], qf[mt][kg],
                             kf[nt >> 1][kg][nt & 1], kf[nt >> 1][kg][(nt & 1) + 2]);

#pragma unroll
        for (int mt = 0; mt < 2; mt++) {
            int r0 = wq0 + mt * 16 + g, r1 = r0 + 8;
#pragma unroll
            for (int nt = 0; nt < 4; nt++) {
                int c0 = kt0 + nt * 8 + 2 * t;
                float p0 = fast_exp2(sc[mt][nt][0] * EXP2S);
                float p1 = fast_exp2(sc[mt][nt][1] * EXP2S);
                float p2 = fast_exp2(sc[mt][nt][2] * EXP2S);
                float p3 = fast_exp2(sc[mt][nt][3] * EXP2S);
                if (c0     > r0) p0 = 0.f;
                if (c0 + 1 > r0) p1 = 0.f;
                if (c0     > r1) p2 = 0.f;
                if (c0 + 1 > r1) p3 = 0.f;
                sc[mt][nt][0] = p0; sc[mt][nt][1] = p1;
                sc[mt][nt][2] = p2; sc[mt][nt][3] = p3;
            }
        }

        unsigned int pa[2][2][4];
#pragma unroll
        for (int mt = 0; mt < 2; mt++)
#pragma unroll
            for (int kg = 0; kg < 2; kg++) {
                __half2 h0 = __floats2half2_rn(sc[mt][2 * kg][0],     sc[mt][2 * kg][1]);
                __half2 h1 = __floats2half2_rn(sc[mt][2 * kg][2],     sc[mt][2 * kg][3]);
                __half2 h2 = __floats2half2_rn(sc[mt][2 * kg + 1][0], sc[mt][2 * kg + 1][1]);
                __half2 h3 = __floats2half2_rn(sc[mt][2 * kg + 1][2], sc[mt][2 * kg + 1][3]);
                pa[mt][kg][0] = h2u(h0);
                pa[mt][kg][1] = h2u(h1);
                pa[mt][kg][2] = h2u(h2);
                pa[mt][kg][3] = h2u(h3);
                float2 f0 = __half22float2(h0), f1 = __half22float2(h1);
                float2 f2 = __half22float2(h2), f3 = __half22float2(h3);
                lsum[mt][0] += f0.x + f0.y + f2.x + f2.y;
                lsum[mt][1] += f1.x + f1.y + f3.x + f3.y;
            }

        unsigned int vf[2][2][4];
        {
            int vrow = ((lane >> 3) & 1) * 8 + (lane & 7);
            int vcol = (lane >> 4) * 8;
#pragma unroll
            for (int np = 0; np < 2; np++)
#pragma unroll
                for (int kg = 0; kg < 2; kg++)
                    ldsm_x4_trans(vf[np][kg], &Vt[kg * 16 + vrow][np * 16 + vcol]);
        }
#pragma unroll
        for (int mt = 0; mt < 2; mt++)
#pragma unroll
            for (int dt = 0; dt < 4; dt++)
#pragma unroll
                for (int kg = 0; kg < 2; kg++)
                    mma_fp16(cacc[mt][dt], pa[mt][kg],
                             vf[dt >> 1][kg][(dt & 1) * 2],
                             vf[dt >> 1][kg][(dt & 1) * 2 + 1]);
    }

#pragma unroll
    for (int mt = 0; mt < 2; mt++)
#pragma unroll
        for (int hf = 0; hf < 2; hf++) {
            float l = lsum[mt][hf];
            l += __shfl_xor_sync(0xffffffffu, l, 1);
            l += __shfl_xor_sync(0xffffffffu, l, 2);
            lsum[mt][hf] = 1.0f / l;
        }

#pragma unroll
    for (int mt = 0; mt < 2; mt++) {
        int r0 = wq0 + mt * 16 + g, r1 = r0 + 8;
        __half* o0 = ctx + ((size_t)r0 * BAT + b) * DIM + h * DH;
        __half* o1 = ctx + ((size_t)r1 * BAT + b) * DIM + h * DH;
        float i0 = lsum[mt][0], i1 = lsum[mt][1];
#pragma unroll
        for (int dt = 0; dt < 4; dt++) {
            int col = dt * 8 + 2 * t;
            *(__half2*)&o0[col] = __floats2half2_rn(cacc[mt][dt][0] * i0,
                                                    cacc[mt][dt][1] * i0);
            *(__half2*)&o1[col] = __floats2half2_rn(cacc[mt][dt][2] * i1,
                                                    cacc[mt][dt][3] * i1);
        }
    }
}

// ---------------- host-side orchestration -----------------------------------
static void run_block(const float* const* P, const __half* wh,
                      float* x, __half* h, __half* qkvb, __half* ctx, __half* mm) {
    layernorm_kernel<__half><<<ROWS, 192>>>(x, P[0], P[1], h);
    {
        dim3 g(QKVN / 64, ROWS / 128);
        gemm_fp16<0, __half><<<g, 256, GSMEM_BYTES>>>(h, wh + WOFF_QKV, P[3],
                                                      nullptr, qkvb, ROWS, QKVN, DIM);
    }
    attention_mma<<<(SEQ / AQB) * BAT * NH, 128>>>(qkvb, ctx);
    {
        dim3 g(DIM / 64, ROWS / 128);
        gemm_fp16<1, float><<<g, 256, GSMEM_BYTES>>>(ctx, wh + WOFF_WO, P[5],
                                                     x, x, ROWS, DIM, DIM);
    }
    layernorm_kernel<__half><<<ROWS, 192>>>(x, P[6], P[7], h);
    {
        dim3 g(FFD / 64, ROWS / 128);
        gemm_fp16<2, __half><<<g, 256, GSMEM_BYTES>>>(h, wh + WOFF_FC, P[9],
                                                      nullptr, mm, ROWS, FFD, DIM);
    }
    {
        dim3 g(DIM / 64, ROWS / 128);
        gemm_fp16<1, float><<<g, 256, GSMEM_BYTES>>>(mm, wh + WOFF_PROJ, P[11],
                                                     x, x, ROWS, DIM, FFD);
    }
}

extern "C" void kernel_launch(void* const* d_in, const int* in_sizes, int n_in,
                              void* d_out, int out_size) {
    (void)in_sizes; (void)n_in;
    const int*   ids = (const int*)d_in[0];
    const float* wte = (const float*)d_in[3];
    const float* wpe = (const float*)d_in[4];
    const float* l0[12], *l1[12];
    for (int i = 0; i < 12; i++) l0[i] = (const float*)d_in[5 + i];
    for (int i = 0; i < 12; i++) l1[i] = (const float*)d_in[17 + i];
    const float* lnfw = (const float*)d_in[29];
    const float* lnfb = (const float*)d_in[30];
    float* out = (float*)d_out;

    float *x;
    __half *h, *qkvb, *ctx, *mm, *wh;
    cudaGetSymbolAddress((void**)&x,    g_x);
    cudaGetSymbolAddress((void**)&h,    g_h);
    cudaGetSymbolAddress((void**)&qkvb, g_qkv);
    cudaGetSymbolAddress((void**)&ctx,  g_ctx);
    cudaGetSymbolAddress((void**)&mm,   g_mm);
    cudaGetSymbolAddress((void**)&wh,   g_wh);

    // one-time weight fp32->fp16 conversion (single kernel, 8 segments)
    {
        WJobs jobs;
        const float* srcs[8] = { l0[2], l0[4], l0[8], l0[10],
                                 l1[2], l1[4], l1[8], l1[10] };
        const unsigned int sizes[8] = {
            QKVN * DIM, DIM * DIM, FFD * DIM, DIM * FFD,
            QKVN * DIM, DIM * DIM, FFD * DIM, DIM * FFD };
        unsigned int acc = 0;
        for (int i = 0; i < 8; i++) {
            jobs.src[i] = (const float4*)srcs[i];
            acc += sizes[i] / 4;
            jobs.end[i] = acc;
        }
        tohalf_all_kernel<<<(acc + 255) / 256, 256>>>(jobs, wh);
    }

    embed_kernel<<<ROWS, 192>>>(ids, wte, wpe, x);
    run_block(l0, wh,          x, h, qkvb, ctx, mm);
    run_block(l1, wh + WLAYER, x, h, qkvb, ctx, mm);
    layernorm_kernel<float><<<ROWS, 192>>>(x, lnfw, lnfb, out);
    (void)out_size;
}

// round 15
// speedup vs baseline: 1.5066x; 1.5066x over previous
#include <cuda_runtime.h>
#include <cuda_fp16.h>
#include <cuda_bf16.h>
#include <cstdint>
#include <math.h>

// Problem constants
#define VSZ 98304
#define SEQ 1536
#define BAT 2
#define DIM 768
#define NH  24
#define DH  32
#define FFD 3072
#define ROWS (SEQ*BAT)        // 3072
#define QKVN (3*DIM)          // 2304
// exp(s*SCALE) = 2^(s*EXP2S), EXP2S = log2(e)/sqrt(32)
#define EXP2S 0.2550348742f

// ---------------- scratch (device globals; no allocations allowed) ----------
__device__ float  g_x  [ROWS * DIM];    // residual stream (fp32)
__device__ __half g_h  [ROWS * DIM];    // LN output (fp16)
__device__ __half g_qkv[ROWS * QKVN];   // qkv projection (fp16)
__device__ __half g_ctx[ROWS * DIM];    // attention context (fp16)
__device__ __half g_mm [ROWS * FFD];    // FC+gelu output (fp16)

// pre-converted fp16 weights: per layer [wqkv | wo | wfc | wproj]
#define WOFF_QKV  0
#define WOFF_WO   (QKVN*DIM)
#define WOFF_FC   (WOFF_WO + DIM*DIM)
#define WOFF_PROJ (WOFF_FC + FFD*DIM)
#define WLAYER    (WOFF_PROJ + DIM*FFD)         // 7077888
__device__ __half g_wh[2 * WLAYER];

__device__ __forceinline__ unsigned int h2u(__half2 h) {
    union { __half2 h; unsigned int u; } cvt;
    cvt.h = h;
    return cvt.u;
}

// ---------------- one-time weight fp32 -> fp16 conversion (single kernel) ----
struct WJobs {
    const float4* src[8];
    unsigned int  end[8];   // cumulative end, in float4 units
};

__global__ void tohalf_all_kernel(WJobs jobs, __half* __restrict__ out) {
    unsigned int i = blockIdx.x * blockDim.x + threadIdx.x;
    if (i >= jobs.end[7]) return;
    int s = 0;
#pragma unroll
    for (int k = 0; k < 7; k++) s += (i >= jobs.end[k]) ? 1 : 0;
    unsigned int base = s ? jobs.end[s - 1] : 0u;
    float4 v = jobs.src[s][i - base];
    __half2* o = (__half2*)out + 2 * (size_t)i;
    o[0] = __floats2half2_rn(v.x, v.y);
    o[1] = __floats2half2_rn(v.z, v.w);
}

// ---------------- embedding ----------------
__global__ void embed_kernel(const int* __restrict__ ids,
                             const float* __restrict__ wte,
                             const float* __restrict__ wpe,
                             float* __restrict__ x) {
    int r = blockIdx.x;            // r = s*B + b
    int s = r / BAT, b = r % BAT;
    int idx = ids[b * SEQ + s];
    const float4* te = (const float4*)(wte + (size_t)idx * DIM);
    const float4* pe = (const float4*)(wpe + (size_t)s * DIM);
    float4* xr = (float4*)(x + (size_t)r * DIM);
    int i = threadIdx.x;           // 192 threads, one float4 each
    float4 a = te[i], p = pe[i];
    xr[i] = make_float4(a.x + p.x, a.y + p.y, a.z + p.z, a.w + p.w);
}

// ---------------- layernorm over D=768 (192 threads x float4) ---------------
template <typename OutT>
__global__ void layernorm_kernel(const float* __restrict__ x,
                                 const float* __restrict__ w,
                                 const float* __restrict__ b,
                                 OutT* __restrict__ out) {
    __shared__ float ssum[6], ssum2[6];
    __shared__ float smu, sinv;
    int r = blockIdx.x;
    int tid = threadIdx.x;                  // 0..191
    float4 v = ((const float4*)(x + (size_t)r * DIM))[tid];
    float s  = (v.x + v.y) + (v.z + v.w);
    float s2 = fmaf(v.x, v.x, fmaf(v.y, v.y, fmaf(v.z, v.z, v.w * v.w)));
#pragma unroll
    for (int o = 16; o; o >>= 1) {
        s  += __shfl_xor_sync(0xffffffffu, s,  o);
        s2 += __shfl_xor_sync(0xffffffffu, s2, o);
    }
    if ((tid & 31) == 0) { ssum[tid >> 5] = s; ssum2[tid >> 5] = s2; }
    __syncthreads();
    if (tid == 0) {
        float S = 0.f, S2 = 0.f;
#pragma unroll
        for (int i = 0; i < 6; i++) { S += ssum[i]; S2 += ssum2[i]; }
        float mu  = S * (1.0f / DIM);
        float var = S2 * (1.0f / DIM) - mu * mu;
        smu = mu;
        sinv = rsqrtf(var + 1e-5f);
    }
    __syncthreads();
    float mu = smu, inv = sinv;
    float4 wv = ((const float4*)w)[tid];
    float4 bv = ((const float4*)b)[tid];
    float o0 = (v.x - mu) * inv * wv.x + bv.x;
    float o1 = (v.y - mu) * inv * wv.y + bv.y;
    float o2 = (v.z - mu) * inv * wv.z + bv.z;
    float o3 = (v.w - mu) * inv * wv.w + bv.w;
    if constexpr (sizeof(OutT) == 2) {
        __half2* orow = (__half2*)(out + (size_t)r * DIM);
        orow[2 * tid]     = __floats2half2_rn(o0, o1);
        orow[2 * tid + 1] = __floats2half2_rn(o2, o3);
    } else {
        ((float4*)(out + (size_t)r * DIM))[tid] = make_float4(o0, o1, o2, o3);
    }
}

// ---------------- fast exp2 on the FMA pipe (no MUFU) ------------------------
// returns 2^t ; caller pre-scales t = score * EXP2S
__device__ __forceinline__ float fast_exp2(float t) {
    float z = t + 12582912.0f;                 // round-to-nearest-int (RN add)
    int   i = __float_as_int(z) - 0x4B400000;  // integer part
    float f = t - (z - 12582912.0f);           // frac in [-0.5, 0.5]
    float p =              1.3333558146e-3f;
    p = fmaf(p, f, 9.6181291076e-3f);
    p = fmaf(p, f, 5.5504108665e-2f);
    p = fmaf(p, f, 2.4022650696e-1f);
    p = fmaf(p, f, 6.9314718056e-1f);
    p = fmaf(p, f, 1.0f);
    return p * __int_as_float((i + 127) << 23);
}

__device__ __forceinline__ void mma_fp16(float* c, const unsigned int* a,
                                         unsigned int b0, unsigned int b1) {
    asm volatile(
        "mma.sync.aligned.m16n8k16.row.col.f32.f16.f16.f32 "
        "{%0,%1,%2,%3}, {%4,%5,%6,%7}, {%8,%9}, {%0,%1,%2,%3};\n"
        : "+f"(c[0]), "+f"(c[1]), "+f"(c[2]), "+f"(c[3])
        : "r"(a[0]), "r"(a[1]), "r"(a[2]), "r"(a[3]), "r"(b0), "r"(b1));
}

__device__ __forceinline__ void ldsm_x4(unsigned int* r, const void* smem) {
    unsigned int addr = (unsigned int)__cvta_generic_to_shared(smem);
    asm volatile(
        "ldmatrix.sync.aligned.m8n8.x4.shared.b16 {%0,%1,%2,%3}, [%4];\n"
        : "=r"(r[0]), "=r"(r[1]), "=r"(r[2]), "=r"(r[3]) : "r"(addr));
}

__device__ __forceinline__ void ldsm_x4_trans(unsigned int* r, const void* smem) {
    unsigned int addr = (unsigned int)__cvta_generic_to_shared(smem);
    asm volatile(
        "ldmatrix.sync.aligned.m8n8.x4.trans.shared.b16 {%0,%1,%2,%3}, [%4];\n"
        : "=r"(r[0]), "=r"(r[1]), "=r"(r[2]), "=r"(r[3]) : "r"(addr));
}

__device__ __forceinline__ void cp_async16(void* smem, const void* gmem) {
    unsigned int s = (unsigned int)__cvta_generic_to_shared(smem);
    asm volatile("cp.async.cg.shared.global [%0], [%1], 16;\n" :: "r"(s), "l"(gmem));
}
#define CP_COMMIT() asm volatile("cp.async.commit_group;\n" ::: "memory")
#define CP_WAIT1()  asm volatile("cp.async.wait_group 1;\n" ::: "memory")

// ---------------- fp16 tensor-core NT GEMM (128x64 tiles, 3 CTA/SM) ----------
// EPI: 0 = bias (OutT=__half), 1 = bias + residual (OutT=float),
//      2 = bias + exact gelu (OutT=__half)
#define HPAD 40
#define ATILE_H (128 * HPAD)              // A halves per stage
#define BTILE_H (64 * HPAD)               // B halves per stage
#define GSMEM_BYTES (3 * (ATILE_H + BTILE_H) * 2)   // 46080 B

template <int EPI, typename OutT>
__global__ void __launch_bounds__(256, 3)
gemm_fp16(const __half* __restrict__ A, const __half* __restrict__ W,
          const float* __restrict__ bias, const float* __restrict__ res,
          OutT* __restrict__ C, int M, int N, int K) {
    extern __shared__ __half sm[];
    // A stage s: sm + s*ATILE_H ; B stage s: sm + 3*ATILE_H + s*BTILE_H

    int m0 = blockIdx.y * 128;
    int n0 = blockIdx.x * 64;
    int tid  = threadIdx.x;
    int warp = tid >> 5, lane = tid & 31;
    int wm = (warp >> 1) * 32;     // 4 warps along M
    int wn = (warp & 1) * 32;      // 2 warps along N
    int g = lane >> 2, t = lane & 3;
    int lrow = lane & 15, lcol = (lane >> 4) * 8;

    float c[2][4][4];
#pragma unroll
    for (int mi = 0; mi < 2; mi++)
#pragma unroll
        for (int nj = 0; nj < 4; nj++)
#pragma unroll
            for (int f = 0; f < 4; f++) c[mi][nj][f] = 0.f;

    int ldrow = tid >> 2, ldc8 = (tid & 3) * 8;   // 64 rows x 4 chunks
    auto load_tile = [&](int s, int k0) {
        __half* As = sm + s * ATILE_H;
        __half* Bs = sm + 3 * ATILE_H + s * BTILE_H;
        cp_async16(&As[ldrow * HPAD + ldc8],
                   &A[(size_t)(m0 + ldrow) * K + k0 + ldc8]);
        cp_async16(&As[(ldrow + 64) * HPAD + ldc8],
                   &A[(size_t)(m0 + ldrow + 64) * K + k0 + ldc8]);
        cp_async16(&Bs[ldrow * HPAD + ldc8],
                   &W[(size_t)(n0 + ldrow) * K + k0 + ldc8]);
    };

    int nk = K >> 5;
    load_tile(0, 0);
    CP_COMMIT();
    load_tile(1, 32);
    CP_COMMIT();

    int s = 0;
    for (int kt = 0; kt < nk; kt++) {
        CP_WAIT1();
        __syncthreads();
        if (kt + 2 < nk) load_tile((s + 2) % 3, (kt + 2) << 5);
        CP_COMMIT();

        const __half* As = sm + s * ATILE_H;
        const __half* Bs = sm + 3 * ATILE_H + s * BTILE_H;
#pragma unroll
        for (int ks = 0; ks < 2; ks++) {
            int k0 = ks * 16 + lcol;
            unsigned int a[2][4], bfr[2][4];
#pragma unroll
            for (int mi = 0; mi < 2; mi++)
                ldsm_x4(a[mi], &As[(wm + mi * 16 + lrow) * HPAD + k0]);
#pragma unroll
            for (int np = 0; np < 2; np++)
                ldsm_x4(bfr[np], &Bs[(wn + np * 16 + lrow) * HPAD + k0]);
#pragma unroll
            for (int mi = 0; mi < 2; mi++)
#pragma unroll
                for (int nj = 0; nj < 4; nj++)
                    mma_fp16(c[mi][nj], a[mi],
                             bfr[nj >> 1][nj & 1], bfr[nj >> 1][(nj & 1) + 2]);
        }
        s = (s + 1) % 3;
    }

#pragma unroll
    for (int mi = 0; mi < 2; mi++) {
        int r0 = m0 + wm + mi * 16 + g;
        int r1 = r0 + 8;
#pragma unroll
        for (int nj = 0; nj < 4; nj++) {
            int col = n0 + wn + nj * 8 + 2 * t;
            float b0 = bias[col], b1 = bias[col + 1];
            float v00 = c[mi][nj][0] + b0, v01 = c[mi][nj][1] + b1;
            float v10 = c[mi][nj][2] + b0, v11 = c[mi][nj][3] + b1;
            if (EPI == 1) {
                v00 += res[(size_t)r0 * N + col];
                v01 += res[(size_t)r0 * N + col + 1];
                v10 += res[(size_t)r1 * N + col];
                v11 += res[(size_t)r1 * N + col + 1];
            }
            if (EPI == 2) {
                v00 = 0.5f * v00 * (1.0f + erff(v00 * 0.7071067811865476f));
                v01 = 0.5f * v01 * (1.0f + erff(v01 * 0.7071067811865476f));
                v10 = 0.5f * v10 * (1.0f + erff(v10 * 0.7071067811865476f));
                v11 = 0.5f * v11 * (1.0f + erff(v11 * 0.7071067811865476f));
            }
            if constexpr (sizeof(OutT) == 2) {
                *(__half2*)&C[(size_t)r0 * N + col] = __floats2half2_rn(v00, v01);
                *(__half2*)&C[(size_t)r1 * N + col] = __floats2half2_rn(v10, v11);
            } else {
                *(float2*)&C[(size_t)r0 * N + col] = make_float2(v00, v01);
                *(float2*)&C[(size_t)r1 * N + col] = make_float2(v10, v11);
            }
        }
    }
}

// ---------------- fp16 MMA causal flash attention (R12 proven 2-D grid) ------
#define AQB 128
#define AKT 32
#define KPAD 40

__global__ void __launch_bounds__(128, 4)
attention_mma(const __half* __restrict__ qkv, __half* __restrict__ ctx) {
    __shared__ __half Qs[AQB][KPAD];   // used only during init
    __shared__ __half Kt[AKT][KPAD];
    __shared__ __half Vt[AKT][KPAD];

    int bh = blockIdx.y;
    int b = bh / NH, h = bh % NH;
    int q0 = blockIdx.x * AQB;
    int tid = threadIdx.x;
    int warp = tid >> 5, lane = tid & 31;
    int g = lane >> 2, t = lane & 3;
    int lrow = lane & 15, lcol = (lane >> 4) * 8;
    int wq0 = q0 + warp * 32;

    {
        const __half* qp = qkv + ((size_t)(q0 + tid) * BAT + b) * QKVN + h * 96;
#pragma unroll
        for (int i = 0; i < 4; i++)
            *(uint4*)&Qs[tid][i * 8] = *(const uint4*)&qp[i * 8];
    }
    __syncthreads();
    unsigned int qf[2][2][4];          // [mt][kg]
#pragma unroll
    for (int mt = 0; mt < 2; mt++)
#pragma unroll
        for (int kg = 0; kg < 2; kg++)
            ldsm_x4(qf[mt][kg], &Qs[warp * 32 + mt * 16 + lrow][kg * 16 + lcol]);

    float cacc[2][4][4];
#pragma unroll
    for (int mt = 0; mt < 2; mt++)
#pragma unroll
        for (int dt = 0; dt < 4; dt++)
#pragma unroll
            for (int f = 0; f < 4; f++) cacc[mt][dt][f] = 0.f;
    float lsum[2][2] = {{0.f, 0.f}, {0.f, 0.f}};

    int kend = q0 + AQB;
    for (int kt0 = 0; kt0 < kend; kt0 += AKT) {
        __syncthreads();
        {   // stage K,V tile: 32 keys x 32 halves each
            int kk = tid >> 2, c8 = (tid & 3) * 8;
            const __half* kp = qkv + ((size_t)(kt0 + kk) * BAT + b) * QKVN + h * 96;
            *(uint4*)&Kt[kk][c8] = *(const uint4*)&kp[DH + c8];
            *(uint4*)&Vt[kk][c8] = *(const uint4*)&kp[2 * DH + c8];
        }
        __syncthreads();

        if (kt0 > wq0 + 31) continue;

        unsigned int kf[2][2][4];
#pragma unroll
        for (int ntp = 0; ntp < 2; ntp++)
#pragma unroll
            for (int kg = 0; kg < 2; kg++)
                ldsm_x4(kf[ntp][kg], &Kt[ntp * 16 + lrow][kg * 16 + lcol]);

        float sc[2][4][4];
#pragma unroll
        for (int mt = 0; mt < 2; mt++)
#pragma unroll
            for (int nt = 0; nt < 4; nt++)
#pragma unroll
                for (int f = 0; f < 4; f++) sc[mt][nt][f] = 0.f;
#pragma unroll
        for (int mt = 0; mt < 2; mt++)
#pragma unroll
            for (int nt = 0; nt < 4; nt++)
#pragma unroll
                for (int kg = 0; kg < 2; kg++)
                    mma_fp16(sc[mt][nt], qf[mt][kg],
                             kf[nt >> 1][kg][nt & 1], kf[nt >> 1][kg][(nt & 1) + 2]);

#pragma unroll
        for (int mt = 0; mt < 2; mt++) {
            int r0 = wq0 + mt * 16 + g, r1 = r0 + 8;
#pragma unroll
            for (int nt = 0; nt < 4; nt++) {
                int c0 = kt0 + nt * 8 + 2 * t;
                float p0 = fast_exp2(sc[mt][nt][0] * EXP2S);
                float p1 = fast_exp2(sc[mt][nt][1] * EXP2S);
                float p2 = fast_exp2(sc[mt][nt][2] * EXP2S);
                float p3 = fast_exp2(sc[mt][nt][3] * EXP2S);
                if (c0     > r0) p0 = 0.f;
                if (c0 + 1 > r0) p1 = 0.f;
                if (c0     > r1) p2 = 0.f;
                if (c0 + 1 > r1) p3 = 0.f;
                sc[mt][nt][0] = p0; sc[mt][nt][1] = p1;
                sc[mt][nt][2] = p2; sc[mt][nt][3] = p3;
            }
        }

        unsigned int pa[2][2][4];
#pragma unroll
        for (int mt = 0; mt < 2; mt++)
#pragma unroll
            for (int kg = 0; kg < 2; kg++) {
                __half2 h0 = __floats2half2_rn(sc[mt][2 * kg][0],     sc[mt][2 * kg][1]);
                __half2 h1 = __floats2half2_rn(sc[mt][2 * kg][2],     sc[mt][2 * kg][3]);
                __half2 h2 = __floats2half2_rn(sc[mt][2 * kg + 1][0], sc[mt][2 * kg + 1][1]);
                __half2 h3 = __floats2half2_rn(sc[mt][2 * kg + 1][2], sc[mt][2 * kg + 1][3]);
                pa[mt][kg][0] = h2u(h0);
                pa[mt][kg][1] = h2u(h1);
                pa[mt][kg][2] = h2u(h2);
                pa[mt][kg][3] = h2u(h3);
                float2 f0 = __half22float2(h0), f1 = __half22float2(h1);
                float2 f2 = __half22float2(h2), f3 = __half22float2(h3);
                lsum[mt][0] += f0.x + f0.y + f2.x + f2.y;
                lsum[mt][1] += f1.x + f1.y + f3.x + f3.y;
            }

        unsigned int vf[2][2][4];
        {
            int vrow = ((lane >> 3) & 1) * 8 + (lane & 7);
            int vcol = (lane >> 4) * 8;
#pragma unroll
            for (int np = 0; np < 2; np++)
#pragma unroll
                for (int kg = 0; kg < 2; kg++)
                    ldsm_x4_trans(vf[np][kg], &Vt[kg * 16 + vrow][np * 16 + vcol]);
        }
#pragma unroll
        for (int mt = 0; mt < 2; mt++)
#pragma unroll
            for (int dt = 0; dt < 4; dt++)
#pragma unroll
                for (int kg = 0; kg < 2; kg++)
                    mma_fp16(cacc[mt][dt], pa[mt][kg],
                             vf[dt >> 1][kg][(dt & 1) * 2],
                             vf[dt >> 1][kg][(dt & 1) * 2 + 1]);
    }

#pragma unroll
    for (int mt = 0; mt < 2; mt++)
#pragma unroll
        for (int hf = 0; hf < 2; hf++) {
            float l = lsum[mt][hf];
            l += __shfl_xor_sync(0xffffffffu, l, 1);
            l += __shfl_xor_sync(0xffffffffu, l, 2);
            lsum[mt][hf] = 1.0f / l;
        }

#pragma unroll
    for (int mt = 0; mt < 2; mt++) {
        int r0 = wq0 + mt * 16 + g, r1 = r0 + 8;
        __half* o0 = ctx + ((size_t)r0 * BAT + b) * DIM + h * DH;
        __half* o1 = ctx + ((size_t)r1 * BAT + b) * DIM + h * DH;
        float i0 = lsum[mt][0], i1 = lsum[mt][1];
#pragma unroll
        for (int dt = 0; dt < 4; dt++) {
            int col = dt * 8 + 2 * t;
            *(__half2*)&o0[col] = __floats2half2_rn(cacc[mt][dt][0] * i0,
                                                    cacc[mt][dt][1] * i0);
            *(__half2*)&o1[col] = __floats2half2_rn(cacc[mt][dt][2] * i1,
                                                    cacc[mt][dt][3] * i1);
        }
    }
}

// ---------------- host-side orchestration -----------------------------------
static void run_block(const float* const* P, const __half* wh,
                      float* x, __half* h, __half* qkvb, __half* ctx, __half* mm) {
    layernorm_kernel<__half><<<ROWS, 192>>>(x, P[0], P[1], h);
    {
        dim3 g(QKVN / 64, ROWS / 128);
        gemm_fp16<0, __half><<<g, 256, GSMEM_BYTES>>>(h, wh + WOFF_QKV, P[3],
                                                      nullptr, qkvb, ROWS, QKVN, DIM);
    }
    {
        dim3 g(SEQ / AQB, BAT * NH);
        attention_mma<<<g, 128>>>(qkvb, ctx);
    }
    {
        dim3 g(DIM / 64, ROWS / 128);
        gemm_fp16<1, float><<<g, 256, GSMEM_BYTES>>>(ctx, wh + WOFF_WO, P[5],
                                                     x, x, ROWS, DIM, DIM);
    }
    layernorm_kernel<__half><<<ROWS, 192>>>(x, P[6], P[7], h);
    {
        dim3 g(FFD / 64, ROWS / 128);
        gemm_fp16<2, __half><<<g, 256, GSMEM_BYTES>>>(h, wh + WOFF_FC, P[9],
                                                      nullptr, mm, ROWS, FFD, DIM);
    }
    {
        dim3 g(DIM / 64, ROWS / 128);
        gemm_fp16<1, float><<<g, 256, GSMEM_BYTES>>>(mm, wh + WOFF_PROJ, P[11],
                                                     x, x, ROWS, DIM, FFD);
    }
}

extern "C" void kernel_launch(void* const* d_in, const int* in_sizes, int n_in,
                              void* d_out, int out_size) {
    (void)in_sizes; (void)n_in;
    const int*   ids = (const int*)d_in[0];
    const float* wte = (const float*)d_in[3];
    const float* wpe = (const float*)d_in[4];
    const float* l0[12], *l1[12];
    for (int i = 0; i < 12; i++) l0[i] = (const float*)d_in[5 + i];
    for (int i = 0; i < 12; i++) l1[i] = (const float*)d_in[17 + i];
    const float* lnfw = (const float*)d_in[29];
    const float* lnfb = (const float*)d_in[30];
    float* out = (float*)d_out;

    float *x;
    __half *h, *qkvb, *ctx, *mm, *wh;
    cudaGetSymbolAddress((void**)&x,    g_x);
    cudaGetSymbolAddress((void**)&h,    g_h);
    cudaGetSymbolAddress((void**)&qkvb, g_qkv);
    cudaGetSymbolAddress((void**)&ctx,  g_ctx);
    cudaGetSymbolAddress((void**)&mm,   g_mm);
    cudaGetSymbolAddress((void**)&wh,   g_wh);

    // one-time weight fp32->fp16 conversion (single kernel, 8 segments)
    {
        WJobs jobs;
        const float* srcs[8] = { l0[2], l0[4], l0[8], l0[10],
                                 l1[2], l1[4], l1[8], l1[10] };
        const unsigned int sizes[8] = {
            QKVN * DIM, DIM * DIM, FFD * DIM, DIM * FFD,
            QKVN * DIM, DIM * DIM, FFD * DIM, DIM * FFD };
        unsigned int acc = 0;
        for (int i = 0; i < 8; i++) {
            jobs.src[i] = (const float4*)srcs[i];
            acc += sizes[i] / 4;
            jobs.end[i] = acc;
        }
        tohalf_all_kernel<<<(acc + 255) / 256, 256>>>(jobs, wh);
    }

    embed_kernel<<<ROWS, 192>>>(ids, wte, wpe, x);
    run_block(l0, wh,          x, h, qkvb, ctx, mm);
    run_block(l1, wh + WLAYER, x, h, qkvb, ctx, mm);
    layernorm_kernel<float><<<ROWS, 192>>>(x, lnfw, lnfb, out);
    (void)out_size;
}

// round 16
// speedup vs baseline: 1.5269x; 1.0135x over previous
#include <cuda_runtime.h>
#include <cuda_fp16.h>
#include <cuda_bf16.h>
#include <cstdint>
#include <math.h>

// Problem constants
#define VSZ 98304
#define SEQ 1536
#define BAT 2
#define DIM 768
#define NH  24
#define DH  32
#define FFD 3072
#define ROWS (SEQ*BAT)        // 3072
#define QKVN (3*DIM)          // 2304
// exp(s*SCALE) = 2^(s*EXP2S), EXP2S = log2(e)/sqrt(32)
#define EXP2S 0.2550348742f

// ---------------- scratch (device globals; no allocations allowed) ----------
__device__ float  g_x  [ROWS * DIM];    // residual stream (fp32)
__device__ __half g_h  [ROWS * DIM];    // LN output (fp16)
__device__ __half g_qkv[ROWS * QKVN];   // qkv projection (fp16)
__device__ __half g_ctx[ROWS * DIM];    // attention context (fp16)
__device__ __half g_mm [ROWS * FFD];    // FC+gelu output (fp16)

// pre-converted fp16 weights: per layer [wqkv | wo | wfc | wproj]
#define WOFF_QKV  0
#define WOFF_WO   (QKVN*DIM)
#define WOFF_FC   (WOFF_WO + DIM*DIM)
#define WOFF_PROJ (WOFF_FC + FFD*DIM)
#define WLAYER    (WOFF_PROJ + DIM*FFD)         // 7077888
__device__ __half g_wh[2 * WLAYER];

__device__ __forceinline__ unsigned int h2u(__half2 h) {
    union { __half2 h; unsigned int u; } cvt;
    cvt.h = h;
    return cvt.u;
}

// ---------------- one-time weight fp32 -> fp16 conversion (single kernel) ----
struct WJobs {
    const float4* src[8];
    unsigned int  end[8];   // cumulative end, in float4 units
};

__global__ void tohalf_all_kernel(WJobs jobs, __half* __restrict__ out) {
    unsigned int i = blockIdx.x * blockDim.x + threadIdx.x;
    if (i >= jobs.end[7]) return;
    int s = 0;
#pragma unroll
    for (int k = 0; k < 7; k++) s += (i >= jobs.end[k]) ? 1 : 0;
    unsigned int base = s ? jobs.end[s - 1] : 0u;
    float4 v = jobs.src[s][i - base];
    __half2* o = (__half2*)out + 2 * (size_t)i;
    o[0] = __floats2half2_rn(v.x, v.y);
    o[1] = __floats2half2_rn(v.z, v.w);
}

// ---------------- embedding ----------------
__global__ void embed_kernel(const int* __restrict__ ids,
                             const float* __restrict__ wte,
                             const float* __restrict__ wpe,
                             float* __restrict__ x) {
    int r = blockIdx.x;            // r = s*B + b
    int s = r / BAT, b = r % BAT;
    int idx = ids[b * SEQ + s];
    const float4* te = (const float4*)(wte + (size_t)idx * DIM);
    const float4* pe = (const float4*)(wpe + (size_t)s * DIM);
    float4* xr = (float4*)(x + (size_t)r * DIM);
    int i = threadIdx.x;           // 192 threads, one float4 each
    float4 a = te[i], p = pe[i];
    xr[i] = make_float4(a.x + p.x, a.y + p.y, a.z + p.z, a.w + p.w);
}

// ---------------- layernorm over D=768 (192 threads x float4) ---------------
template <typename OutT>
__global__ void layernorm_kernel(const float* __restrict__ x,
                                 const float* __restrict__ w,
                                 const float* __restrict__ b,
                                 OutT* __restrict__ out) {
    __shared__ float ssum[6], ssum2[6];
    __shared__ float smu, sinv;
    int r = blockIdx.x;
    int tid = threadIdx.x;                  // 0..191
    float4 v = ((const float4*)(x + (size_t)r * DIM))[tid];
    float s  = (v.x + v.y) + (v.z + v.w);
    float s2 = fmaf(v.x, v.x, fmaf(v.y, v.y, fmaf(v.z, v.z, v.w * v.w)));
#pragma unroll
    for (int o = 16; o; o >>= 1) {
        s  += __shfl_xor_sync(0xffffffffu, s,  o);
        s2 += __shfl_xor_sync(0xffffffffu, s2, o);
    }
    if ((tid & 31) == 0) { ssum[tid >> 5] = s; ssum2[tid >> 5] = s2; }
    __syncthreads();
    if (tid == 0) {
        float S = 0.f, S2 = 0.f;
#pragma unroll
        for (int i = 0; i < 6; i++) { S += ssum[i]; S2 += ssum2[i]; }
        float mu  = S * (1.0f / DIM);
        float var = S2 * (1.0f / DIM) - mu * mu;
        smu = mu;
        sinv = rsqrtf(var + 1e-5f);
    }
    __syncthreads();
    float mu = smu, inv = sinv;
    float4 wv = ((const float4*)w)[tid];
    float4 bv = ((const float4*)b)[tid];
    float o0 = (v.x - mu) * inv * wv.x + bv.x;
    float o1 = (v.y - mu) * inv * wv.y + bv.y;
    float o2 = (v.z - mu) * inv * wv.z + bv.z;
    float o3 = (v.w - mu) * inv * wv.w + bv.w;
    if constexpr (sizeof(OutT) == 2) {
        __half2* orow = (__half2*)(out + (size_t)r * DIM);
        orow[2 * tid]     = __floats2half2_rn(o0, o1);
        orow[2 * tid + 1] = __floats2half2_rn(o2, o3);
    } else {
        ((float4*)(out + (size_t)r * DIM))[tid] = make_float4(o0, o1, o2, o3);
    }
}

// ---------------- fast exp2 on the FMA pipe (no MUFU) ------------------------
// returns 2^t ; caller pre-scales t = score * EXP2S
__device__ __forceinline__ float fast_exp2(float t) {
    float z = t + 12582912.0f;                 // round-to-nearest-int (RN add)
    int   i = __float_as_int(z) - 0x4B400000;  // integer part
    float f = t - (z - 12582912.0f);           // frac in [-0.5, 0.5]
    float p =              1.3333558146e-3f;
    p = fmaf(p, f, 9.6181291076e-3f);
    p = fmaf(p, f, 5.5504108665e-2f);
    p = fmaf(p, f, 2.4022650696e-1f);
    p = fmaf(p, f, 6.9314718056e-1f);
    p = fmaf(p, f, 1.0f);
    return p * __int_as_float((i + 127) << 23);
}

__device__ __forceinline__ void mma_fp16(float* c, const unsigned int* a,
                                         unsigned int b0, unsigned int b1) {
    asm volatile(
        "mma.sync.aligned.m16n8k16.row.col.f32.f16.f16.f32 "
        "{%0,%1,%2,%3}, {%4,%5,%6,%7}, {%8,%9}, {%0,%1,%2,%3};\n"
        : "+f"(c[0]), "+f"(c[1]), "+f"(c[2]), "+f"(c[3])
        : "r"(a[0]), "r"(a[1]), "r"(a[2]), "r"(a[3]), "r"(b0), "r"(b1));
}

__device__ __forceinline__ void ldsm_x4(unsigned int* r, const void* smem) {
    unsigned int addr = (unsigned int)__cvta_generic_to_shared(smem);
    asm volatile(
        "ldmatrix.sync.aligned.m8n8.x4.shared.b16 {%0,%1,%2,%3}, [%4];\n"
        : "=r"(r[0]), "=r"(r[1]), "=r"(r[2]), "=r"(r[3]) : "r"(addr));
}

__device__ __forceinline__ void ldsm_x4_trans(unsigned int* r, const void* smem) {
    unsigned int addr = (unsigned int)__cvta_generic_to_shared(smem);
    asm volatile(
        "ldmatrix.sync.aligned.m8n8.x4.trans.shared.b16 {%0,%1,%2,%3}, [%4];\n"
        : "=r"(r[0]), "=r"(r[1]), "=r"(r[2]), "=r"(r[3]) : "r"(addr));
}

__device__ __forceinline__ void cp_async16(void* smem, const void* gmem) {
    unsigned int s = (unsigned int)__cvta_generic_to_shared(smem);
    asm volatile("cp.async.cg.shared.global [%0], [%1], 16;\n" :: "r"(s), "l"(gmem));
}
#define CP_COMMIT() asm volatile("cp.async.commit_group;\n" ::: "memory")
#define CP_WAIT1()  asm volatile("cp.async.wait_group 1;\n" ::: "memory")
#define CP_WAIT0()  asm volatile("cp.async.wait_group 0;\n" ::: "memory")

// ---------------- fp16 tensor-core NT GEMM (128x64 tiles, 3 CTA/SM) ----------
// EPI: 0 = bias (OutT=__half), 1 = bias + residual (OutT=float),
//      2 = bias + exact gelu (OutT=__half)
#define HPAD 40
#define ATILE_H (128 * HPAD)              // A halves per stage
#define BTILE_H (64 * HPAD)               // B halves per stage
#define GSMEM_BYTES (3 * (ATILE_H + BTILE_H) * 2)   // 46080 B

template <int EPI, typename OutT>
__global__ void __launch_bounds__(256, 3)
gemm_fp16(const __half* __restrict__ A, const __half* __restrict__ W,
          const float* __restrict__ bias, const float* __restrict__ res,
          OutT* __restrict__ C, int M, int N, int K) {
    extern __shared__ __half sm[];
    // A stage s: sm + s*ATILE_H ; B stage s: sm + 3*ATILE_H + s*BTILE_H

    int m0 = blockIdx.y * 128;
    int n0 = blockIdx.x * 64;
    int tid  = threadIdx.x;
    int warp = tid >> 5, lane = tid & 31;
    int wm = (warp >> 1) * 32;     // 4 warps along M
    int wn = (warp & 1) * 32;      // 2 warps along N
    int g = lane >> 2, t = lane & 3;
    int lrow = lane & 15, lcol = (lane >> 4) * 8;

    float c[2][4][4];
#pragma unroll
    for (int mi = 0; mi < 2; mi++)
#pragma unroll
        for (int nj = 0; nj < 4; nj++)
#pragma unroll
            for (int f = 0; f < 4; f++) c[mi][nj][f] = 0.f;

    int ldrow = tid >> 2, ldc8 = (tid & 3) * 8;   // 64 rows x 4 chunks
    auto load_tile = [&](int s, int k0) {
        __half* As = sm + s * ATILE_H;
        __half* Bs = sm + 3 * ATILE_H + s * BTILE_H;
        cp_async16(&As[ldrow * HPAD + ldc8],
                   &A[(size_t)(m0 + ldrow) * K + k0 + ldc8]);
        cp_async16(&As[(ldrow + 64) * HPAD + ldc8],
                   &A[(size_t)(m0 + ldrow + 64) * K + k0 + ldc8]);
        cp_async16(&Bs[ldrow * HPAD + ldc8],
                   &W[(size_t)(n0 + ldrow) * K + k0 + ldc8]);
    };

    int nk = K >> 5;
    load_tile(0, 0);
    CP_COMMIT();
    load_tile(1, 32);
    CP_COMMIT();

    int s = 0;
    for (int kt = 0; kt < nk; kt++) {
        CP_WAIT1();
        __syncthreads();
        if (kt + 2 < nk) load_tile((s + 2) % 3, (kt + 2) << 5);
        CP_COMMIT();

        const __half* As = sm + s * ATILE_H;
        const __half* Bs = sm + 3 * ATILE_H + s * BTILE_H;
#pragma unroll
        for (int ks = 0; ks < 2; ks++) {
            int k0 = ks * 16 + lcol;
            unsigned int a[2][4], bfr[2][4];
#pragma unroll
            for (int mi = 0; mi < 2; mi++)
                ldsm_x4(a[mi], &As[(wm + mi * 16 + lrow) * HPAD + k0]);
#pragma unroll
            for (int np = 0; np < 2; np++)
                ldsm_x4(bfr[np], &Bs[(wn + np * 16 + lrow) * HPAD + k0]);
#pragma unroll
            for (int mi = 0; mi < 2; mi++)
#pragma unroll
                for (int nj = 0; nj < 4; nj++)
                    mma_fp16(c[mi][nj], a[mi],
                             bfr[nj >> 1][nj & 1], bfr[nj >> 1][(nj & 1) + 2]);
        }
        s = (s + 1) % 3;
    }

#pragma unroll
    for (int mi = 0; mi < 2; mi++) {
        int r0 = m0 + wm + mi * 16 + g;
        int r1 = r0 + 8;
#pragma unroll
        for (int nj = 0; nj < 4; nj++) {
            int col = n0 + wn + nj * 8 + 2 * t;
            float b0 = bias[col], b1 = bias[col + 1];
            float v00 = c[mi][nj][0] + b0, v01 = c[mi][nj][1] + b1;
            float v10 = c[mi][nj][2] + b0, v11 = c[mi][nj][3] + b1;
            if (EPI == 1) {
                v00 += res[(size_t)r0 * N + col];
                v01 += res[(size_t)r0 * N + col + 1];
                v10 += res[(size_t)r1 * N + col];
                v11 += res[(size_t)r1 * N + col + 1];
            }
            if (EPI == 2) {
                v00 = 0.5f * v00 * (1.0f + erff(v00 * 0.7071067811865476f));
                v01 = 0.5f * v01 * (1.0f + erff(v01 * 0.7071067811865476f));
                v10 = 0.5f * v10 * (1.0f + erff(v10 * 0.7071067811865476f));
                v11 = 0.5f * v11 * (1.0f + erff(v11 * 0.7071067811865476f));
            }
            if constexpr (sizeof(OutT) == 2) {
                *(__half2*)&C[(size_t)r0 * N + col] = __floats2half2_rn(v00, v01);
                *(__half2*)&C[(size_t)r1 * N + col] = __floats2half2_rn(v10, v11);
            } else {
                *(float2*)&C[(size_t)r0 * N + col] = make_float2(v00, v01);
                *(float2*)&C[(size_t)r1 * N + col] = make_float2(v10, v11);
            }
        }
    }
}

// ---------------- fp16 MMA causal flash attention ----------------------------
// R12 2-D grid + cp.async double-buffered K/V (one barrier per key tile).
#define AQB 128
#define AKT 32
#define KPAD 40

__global__ void __launch_bounds__(128, 4)
attention_mma(const __half* __restrict__ qkv, __half* __restrict__ ctx) {
    __shared__ __half Qs[AQB][KPAD];   // used only during init
    __shared__ __half Kt[2][AKT][KPAD];
    __shared__ __half Vt[2][AKT][KPAD];

    int bh = blockIdx.y;
    int b = bh / NH, h = bh % NH;
    int q0 = blockIdx.x * AQB;
    int tid = threadIdx.x;
    int warp = tid >> 5, lane = tid & 31;
    int g = lane >> 2, t = lane & 3;
    int lrow = lane & 15, lcol = (lane >> 4) * 8;
    int kvrow = tid >> 2, kvc8 = (tid & 3) * 8;
    int wq0 = q0 + warp * 32;

    // preload K/V tile 0 (overlaps with Q staging below)
    {
        const __half* kp = qkv + ((size_t)kvrow * BAT + b) * QKVN + h * 96;
        cp_async16(&Kt[0][kvrow][kvc8], &kp[DH + kvc8]);
        cp_async16(&Vt[0][kvrow][kvc8], &kp[2 * DH + kvc8]);
    }
    CP_COMMIT();

    {
        const __half* qp = qkv + ((size_t)(q0 + tid) * BAT + b) * QKVN + h * 96;
#pragma unroll
        for (int i = 0; i < 4; i++)
            *(uint4*)&Qs[tid][i * 8] = *(const uint4*)&qp[i * 8];
    }
    __syncthreads();
    unsigned int qf[2][2][4];          // [mt][kg]
#pragma unroll
    for (int mt = 0; mt < 2; mt++)
#pragma unroll
        for (int kg = 0; kg < 2; kg++)
            ldsm_x4(qf[mt][kg], &Qs[warp * 32 + mt * 16 + lrow][kg * 16 + lcol]);

    float cacc[2][4][4];
#pragma unroll
    for (int mt = 0; mt < 2; mt++)
#pragma unroll
        for (int dt = 0; dt < 4; dt++)
#pragma unroll
            for (int f = 0; f < 4; f++) cacc[mt][dt][f] = 0.f;
    float lsum[2][2] = {{0.f, 0.f}, {0.f, 0.f}};

    int nkt = (q0 + AQB) / AKT;        // key tiles needed by this block
    int buf = 0;
    for (int kt = 0; kt < nkt; kt++) {
        CP_WAIT0();
        __syncthreads();   // tile kt visible; compute(kt-1) done -> buf^1 free
        if (kt + 1 < nkt) {
            const __half* kp = qkv +
                ((size_t)((kt + 1) * AKT + kvrow) * BAT + b) * QKVN + h * 96;
            cp_async16(&Kt[buf ^ 1][kvrow][kvc8], &kp[DH + kvc8]);
            cp_async16(&Vt[buf ^ 1][kvrow][kvc8], &kp[2 * DH + kvc8]);
            CP_COMMIT();
        }

        int kt0 = kt * AKT;
        if (kt0 <= wq0 + 31) {
            unsigned int kf[2][2][4];
#pragma unroll
            for (int ntp = 0; ntp < 2; ntp++)
#pragma unroll
                for (int kg = 0; kg < 2; kg++)
                    ldsm_x4(kf[ntp][kg], &Kt[buf][ntp * 16 + lrow][kg * 16 + lcol]);

            float sc[2][4][4];
#pragma unroll
            for (int mt = 0; mt < 2; mt++)
#pragma unroll
                for (int nt = 0; nt < 4; nt++)
#pragma unroll
                    for (int f = 0; f < 4; f++) sc[mt][nt][f] = 0.f;
#pragma unroll
            for (int mt = 0; mt < 2; mt++)
#pragma unroll
                for (int nt = 0; nt < 4; nt++)
#pragma unroll
                    for (int kg = 0; kg < 2; kg++)
                        mma_fp16(sc[mt][nt], qf[mt][kg],
                                 kf[nt >> 1][kg][nt & 1],
                                 kf[nt >> 1][kg][(nt & 1) + 2]);

#pragma unroll
            for (int mt = 0; mt < 2; mt++) {
                int r0 = wq0 + mt * 16 + g, r1 = r0 + 8;
#pragma unroll
                for (int nt = 0; nt < 4; nt++) {
                    int c0 = kt0 + nt * 8 + 2 * t;
                    float p0 = fast_exp2(sc[mt][nt][0] * EXP2S);
                    float p1 = fast_exp2(sc[mt][nt][1] * EXP2S);
                    float p2 = fast_exp2(sc[mt][nt][2] * EXP2S);
                    float p3 = fast_exp2(sc[mt][nt][3] * EXP2S);
                    if (c0     > r0) p0 = 0.f;
                    if (c0 + 1 > r0) p1 = 0.f;
                    if (c0     > r1) p2 = 0.f;
                    if (c0 + 1 > r1) p3 = 0.f;
                    sc[mt][nt][0] = p0; sc[mt][nt][1] = p1;
                    sc[mt][nt][2] = p2; sc[mt][nt][3] = p3;
                }
            }

            unsigned int pa[2][2][4];
#pragma unroll
            for (int mt = 0; mt < 2; mt++)
#pragma unroll
                for (int kg = 0; kg < 2; kg++) {
                    __half2 h0 = __floats2half2_rn(sc[mt][2 * kg][0],     sc[mt][2 * kg][1]);
                    __half2 h1 = __floats2half2_rn(sc[mt][2 * kg][2],     sc[mt][2 * kg][3]);
                    __half2 h2 = __floats2half2_rn(sc[mt][2 * kg + 1][0], sc[mt][2 * kg + 1][1]);
                    __half2 h3 = __floats2half2_rn(sc[mt][2 * kg + 1][2], sc[mt][2 * kg + 1][3]);
                    pa[mt][kg][0] = h2u(h0);
                    pa[mt][kg][1] = h2u(h1);
                    pa[mt][kg][2] = h2u(h2);
                    pa[mt][kg][3] = h2u(h3);
                    float2 f0 = __half22float2(h0), f1 = __half22float2(h1);
                    float2 f2 = __half22float2(h2), f3 = __half22float2(h3);
                    lsum[mt][0] += f0.x + f0.y + f2.x + f2.y;
                    lsum[mt][1] += f1.x + f1.y + f3.x + f3.y;
                }

            unsigned int vf[2][2][4];
            {
                int vrow = ((lane >> 3) & 1) * 8 + (lane & 7);
                int vcol = (lane >> 4) * 8;
#pragma unroll
                for (int np = 0; np < 2; np++)
#pragma unroll
                    for (int kg = 0; kg < 2; kg++)
                        ldsm_x4_trans(vf[np][kg],
                                      &Vt[buf][kg * 16 + vrow][np * 16 + vcol]);
            }
#pragma unroll
            for (int mt = 0; mt < 2; mt++)
#pragma unroll
                for (int dt = 0; dt < 4; dt++)
#pragma unroll
                    for (int kg = 0; kg < 2; kg++)
                        mma_fp16(cacc[mt][dt], pa[mt][kg],
                                 vf[dt >> 1][kg][(dt & 1) * 2],
                                 vf[dt >> 1][kg][(dt & 1) * 2 + 1]);
        }
        buf ^= 1;
    }

#pragma unroll
    for (int mt = 0; mt < 2; mt++)
#pragma unroll
        for (int hf = 0; hf < 2; hf++) {
            float l = lsum[mt][hf];
            l += __shfl_xor_sync(0xffffffffu, l, 1);
            l += __shfl_xor_sync(0xffffffffu, l, 2);
            lsum[mt][hf] = 1.0f / l;
        }

#pragma unroll
    for (int mt = 0; mt < 2; mt++) {
        int r0 = wq0 + mt * 16 + g, r1 = r0 + 8;
        __half* o0 = ctx + ((size_t)r0 * BAT + b) * DIM + h * DH;
        __half* o1 = ctx + ((size_t)r1 * BAT + b) * DIM + h * DH;
        float i0 = lsum[mt][0], i1 = lsum[mt][1];
#pragma unroll
        for (int dt = 0; dt < 4; dt++) {
            int col = dt * 8 + 2 * t;
            *(__half2*)&o0[col] = __floats2half2_rn(cacc[mt][dt][0] * i0,
                                                    cacc[mt][dt][1] * i0);
            *(__half2*)&o1[col] = __floats2half2_rn(cacc[mt][dt][2] * i1,
                                                    cacc[mt][dt][3] * i1);
        }
    }
}

// ---------------- host-side orchestration -----------------------------------
static void run_block(const float* const* P, const __half* wh,
                      float* x, __half* h, __half* qkvb, __half* ctx, __half* mm) {
    layernorm_kernel<__half><<<ROWS, 192>>>(x, P[0], P[1], h);
    {
        dim3 g(QKVN / 64, ROWS / 128);
        gemm_fp16<0, __half><<<g, 256, GSMEM_BYTES>>>(h, wh + WOFF_QKV, P[3],
                                                      nullptr, qkvb, ROWS, QKVN, DIM);
    }
    {
        dim3 g(SEQ / AQB, BAT * NH);
        attention_mma<<<g, 128>>>(qkvb, ctx);
    }
    {
        dim3 g(DIM / 64, ROWS / 128);
        gemm_fp16<1, float><<<g, 256, GSMEM_BYTES>>>(ctx, wh + WOFF_WO, P[5],
                                                     x, x, ROWS, DIM, DIM);
    }
    layernorm_kernel<__half><<<ROWS, 192>>>(x, P[6], P[7], h);
    {
        dim3 g(FFD / 64, ROWS / 128);
        gemm_fp16<2, __half><<<g, 256, GSMEM_BYTES>>>(h, wh + WOFF_FC, P[9],
                                                      nullptr, mm, ROWS, FFD, DIM);
    }
    {
        dim3 g(DIM / 64, ROWS / 128);
        gemm_fp16<1, float><<<g, 256, GSMEM_BYTES>>>(mm, wh + WOFF_PROJ, P[11],
                                                     x, x, ROWS, DIM, FFD);
    }
}

extern "C" void kernel_launch(void* const* d_in, const int* in_sizes, int n_in,
                              void* d_out, int out_size) {
    (void)in_sizes; (void)n_in;
    const int*   ids = (const int*)d_in[0];
    const float* wte = (const float*)d_in[3];
    const float* wpe = (const float*)d_in[4];
    const float* l0[12], *l1[12];
    for (int i = 0; i < 12; i++) l0[i] = (const float*)d_in[5 + i];
    for (int i = 0; i < 12; i++) l1[i] = (const float*)d_in[17 + i];
    const float* lnfw = (const float*)d_in[29];
    const float* lnfb = (const float*)d_in[30];
    float* out = (float*)d_out;

    float *x;
    __half *h, *qkvb, *ctx, *mm, *wh;
    cudaGetSymbolAddress((void**)&x,    g_x);
    cudaGetSymbolAddress((void**)&h,    g_h);
    cudaGetSymbolAddress((void**)&qkvb, g_qkv);
    cudaGetSymbolAddress((void**)&ctx,  g_ctx);
    cudaGetSymbolAddress((void**)&mm,   g_mm);
    cudaGetSymbolAddress((void**)&wh,   g_wh);

    // one-time weight fp32->fp16 conversion (single kernel, 8 segments)
    {
        WJobs jobs;
        const float* srcs[8] = { l0[2], l0[4], l0[8], l0[10],
                                 l1[2], l1[4], l1[8], l1[10] };
        const unsigned int sizes[8] = {
            QKVN * DIM, DIM * DIM, FFD * DIM, DIM * FFD,
            QKVN * DIM, DIM * DIM, FFD * DIM, DIM * FFD };
        unsigned int acc = 0;
        for (int i = 0; i < 8; i++) {
            jobs.src[i] = (const float4*)srcs[i];
            acc += sizes[i] / 4;
            jobs.end[i] = acc;
        }
        tohalf_all_kernel<<<(acc + 255) / 256, 256>>>(jobs, wh);
    }

    embed_kernel<<<ROWS, 192>>>(ids, wte, wpe, x);
    run_block(l0, wh,          x, h, qkvb, ctx, mm);
    run_block(l1, wh + WLAYER, x, h, qkvb, ctx, mm);
    layernorm_kernel<float><<<ROWS, 192>>>(x, lnfw, lnfb, out);
    (void)out_size;
}